// round 13
// baseline (speedup 1.0000x reference)
#include <cuda_runtime.h>
#include <cuda_fp16.h>
#include <cstdint>

#define NU 50000
#define NN 80000
#define NE 1600000
#define NB_SCAN 79   // ceil(80000/1024)
#define NCOL_PAD (NE + 7 * NN)

// ---------------- scratch (device globals; no allocation allowed) ----------
__device__ int    g_deg[NN];
__device__ int    g_off[NN + 1];      // PADDED offsets (multiples of 8)
__device__ int    g_cur[NN + 1];
__device__ unsigned long long g_state[NB_SCAN];
__device__ int    g_col[NCOL_PAD];
// interleaved feature storage: [node][towerA 32 half2][towerB 32 half2]
// row NN = dummy zero row (gather target for CSR padding)
__device__ __half2 g_x[(NN + 8) * 64];
__device__ __half2 g_agg[NN * 64];
__device__ __half2 g_idh[NN * 32];

__device__ __forceinline__ float leaky(float x) {
    return fmaxf(x, 0.01f * x);
}

__device__ __forceinline__ float2 add2(float2 a, float2 b) {
    unsigned long long ra = *reinterpret_cast<unsigned long long*>(&a);
    unsigned long long rb = *reinterpret_cast<unsigned long long*>(&b);
    unsigned long long rd;
    asm("add.rn.f32x2 %0, %1, %2;" : "=l"(rd) : "l"(ra), "l"(rb));
    return *reinterpret_cast<float2*>(&rd);
}

// ------------- launch 1: normalize + id->half + edge histogram --------------
__global__ void k_init_hist(const float* __restrict__ v_pref, const float* __restrict__ v_feat,
                            const float* __restrict__ t_pref, const float* __restrict__ t_feat,
                            const float* __restrict__ id_emb,
                            const int* __restrict__ row) {
    int gid = blockIdx.x * blockDim.x + threadIdx.x;
    if (gid < NE) atomicAdd(&g_deg[row[gid]], 1);
    if (gid < 64) g_x[NN * 64 + gid] = __float2half2_rn(0.f);   // dummy zero row
    int w = gid >> 5;
    int lane = gid & 31;
    if (w < NN) {
        float2 iv = ((const float2*)id_emb)[w * 32 + lane];
        g_idh[w * 32 + lane] = __float22half2_rn(iv);
    }
    if (w >= 2 * NN) return;
    int tower = (w >= NN) ? 1 : 0;
    int n = w - tower * NN;
    const float2* src;
    if (tower == 0)
        src = (n < NU) ? (const float2*)v_pref + n * 32 : (const float2*)v_feat + (n - NU) * 32;
    else
        src = (n < NU) ? (const float2*)t_pref + n * 32 : (const float2*)t_feat + (n - NU) * 32;
    float2 v = src[lane];
    float ss = v.x * v.x + v.y * v.y;
#pragma unroll
    for (int o = 16; o > 0; o >>= 1) ss += __shfl_xor_sync(0xffffffffu, ss, o);
    float inv = 1.0f / fmaxf(sqrtf(ss), 1e-12f);
    g_x[n * 64 + tower * 32 + lane] = __float22half2_rn(make_float2(v.x * inv, v.y * inv));
}

// ------------- launch 2: scan of PADDED degrees + pad-slot fill --------------
__global__ void k_scan() {
    __shared__ int s[1024];
    __shared__ int s_prev;
    int tid = threadIdx.x;
    int i = blockIdx.x * 1024 + tid;
    int dv = (i < NN) ? g_deg[i] : 0;
    int v = (dv + 7) & ~7;             // padded degree
    s[tid] = v;
    __syncthreads();
#pragma unroll
    for (int off = 1; off < 1024; off <<= 1) {
        int t = (tid >= off) ? s[tid - off] : 0;
        __syncthreads();
        s[tid] += t;
        __syncthreads();
    }
    if (tid == 0) {
        unsigned long long mine = (1ULL << 32) | (unsigned)s[1023];
        atomicExch(&g_state[blockIdx.x], mine);
    }
    if (tid < 32) {
        int sum = 0;
        for (int j = tid; j < blockIdx.x; j += 32) {
            unsigned long long st;
            do { st = atomicAdd(&g_state[j], 0ULL); } while (!(st >> 32));
            sum += (int)(unsigned)st;
        }
#pragma unroll
        for (int o = 16; o > 0; o >>= 1) sum += __shfl_xor_sync(0xffffffffu, sum, o);
        if (tid == 0) s_prev = sum;
    }
    __syncthreads();
    int val = s[tid] + s_prev;          // inclusive padded offset (= off[i+1])
    if (i < NN) {
        g_off[i + 1] = val;
        g_cur[i + 1] = val;
        for (int p = val - (v - dv); p < val; p++) g_col[p] = NN;
    }
    if (i == 0) { g_off[0] = 0; g_cur[0] = 0; }
}

// ------------- launch 3: CSR fill -------------------------------------------
__global__ void k_fill(const int* __restrict__ row, const int* __restrict__ col) {
    int e = blockIdx.x * blockDim.x + threadIdx.x;
    if (e < NE) {
        int r = row[e];
        int p = atomicAdd(&g_cur[r], 1);
        g_col[p] = col[e];
    }
}

// ------------- aggregation: warp per TWO rows, both towers -------------------
// R11-proven gather form: per neighbor two 1-line LDG.32 streams (towerA, +128).
__device__ __forceinline__ void quadAB(const char* xb, int4 c, float2& A, float2& B) {
    const char* p0 = xb + ((unsigned)c.x << 8);
    const char* p1 = xb + ((unsigned)c.y << 8);
    const char* p2 = xb + ((unsigned)c.z << 8);
    const char* p3 = xb + ((unsigned)c.w << 8);
    __half2 a0 = *(const __half2*)p0;
    __half2 a1 = *(const __half2*)p1;
    __half2 a2 = *(const __half2*)p2;
    __half2 a3 = *(const __half2*)p3;
    __half2 b0 = *(const __half2*)(p0 + 128);
    __half2 b1 = *(const __half2*)(p1 + 128);
    __half2 b2 = *(const __half2*)(p2 + 128);
    __half2 b3 = *(const __half2*)(p3 + 128);
    __half2 qA = __hadd2(__hadd2(a0, a1), __hadd2(a2, a3));
    __half2 qB = __hadd2(__hadd2(b0, b1), __hadd2(b2, b3));
    A = add2(A, __half22float2(qA));
    B = add2(B, __half22float2(qB));
}

__device__ __forceinline__ void oct(const char* xb, int e, float2& A, float2& B) {
    int4 ca = *(const int4*)(g_col + e);
    int4 cb = *(const int4*)(g_col + e + 4);
    quadAB(xb, ca, A, B);
    quadAB(xb, cb, A, B);
}

__global__ void __launch_bounds__(512)
k_agg() {
    int gw = (blockIdx.x * 512 + threadIdx.x) >> 5;
    int r0 = gw * 2;
    if (r0 >= NN) return;
    int r1 = r0 + 1;
    int lane = threadIdx.x & 31;
    const char* xb = (const char*)g_x + lane * 4;

    int e0 = g_off[r0], end0 = g_off[r0 + 1];
    int e1 = end0,      end1 = g_off[r0 + 2];   // contiguous segments
    float2 A0 = {0.f, 0.f}, B0 = {0.f, 0.f};
    float2 A1 = {0.f, 0.f}, B1 = {0.f, 0.f};

    // interleaved: two independent 8-edge streams per iteration (MLP ~32)
    while (e0 < end0 && e1 < end1) {
        oct(xb, e0, A0, B0);
        oct(xb, e1, A1, B1);
        e0 += 8; e1 += 8;
    }
    for (; e0 < end0; e0 += 8) oct(xb, e0, A0, B0);
    for (; e1 < end1; e1 += 8) oct(xb, e1, A1, B1);

    float i0 = __fdividef(1.0f, (float)g_deg[r0]);
    float i1 = __fdividef(1.0f, (float)g_deg[r1]);
    g_agg[r0 * 64 + lane]      = __float22half2_rn(make_float2(A0.x * i0, A0.y * i0));
    g_agg[r0 * 64 + 32 + lane] = __float22half2_rn(make_float2(B0.x * i0, B0.y * i0));
    g_agg[r1 * 64 + lane]      = __float22half2_rn(make_float2(A1.x * i1, A1.y * i1));
    g_agg[r1 * 64 + 32 + lane] = __float22half2_rn(make_float2(B1.x * i1, B1.y * i1));
}

// ------------- dense via tensor cores (mma.sync m16n8k16 f16->f32) ----------
__device__ __forceinline__ void ldmA(uint32_t addr, uint32_t& a0, uint32_t& a1,
                                     uint32_t& a2, uint32_t& a3) {
    asm volatile("ldmatrix.sync.aligned.m8n8.x4.shared.b16 {%0,%1,%2,%3}, [%4];"
                 : "=r"(a0), "=r"(a1), "=r"(a2), "=r"(a3) : "r"(addr));
}
__device__ __forceinline__ void ldmB(uint32_t addr, uint32_t& b0, uint32_t& b1) {
    asm volatile("ldmatrix.sync.aligned.m8n8.x2.trans.shared.b16 {%0,%1}, [%2];"
                 : "=r"(b0), "=r"(b1) : "r"(addr));
}
__device__ __forceinline__ void hmma(float& c0, float& c1, float& c2, float& c3,
                                     uint32_t a0, uint32_t a1, uint32_t a2, uint32_t a3,
                                     uint32_t b0, uint32_t b1) {
    asm volatile("mma.sync.aligned.m16n8k16.row.col.f32.f16.f16.f32 "
                 "{%0,%1,%2,%3}, {%4,%5,%6,%7}, {%8,%9}, {%0,%1,%2,%3};"
                 : "+f"(c0), "+f"(c1), "+f"(c2), "+f"(c3)
                 : "r"(a0), "r"(a1), "r"(a2), "r"(a3), "r"(b0), "r"(b1));
}

__device__ __forceinline__ void mv_mma(uint32_t uA, uint32_t uWm, float* c, int lane) {
    int r = lane & 15;
    int hiA = lane >> 4;
    int rsw = r & 7;
#pragma unroll
    for (int s = 0; s < 4; s++) {
        uint32_t a0, a1, a2, a3;
        ldmA(uA + r * 128 + (((2 * s + hiA) ^ rsw) << 4), a0, a1, a2, a3);
        uint32_t rowB = uWm + (16 * s + r) * 128;
#pragma unroll
        for (int j = 0; j < 8; j++) {
            uint32_t b0, b1;
            ldmB(rowB + ((j ^ rsw) << 4), b0, b1);
            hmma(c[j * 4], c[j * 4 + 1], c[j * 4 + 2], c[j * 4 + 3],
                 a0, a1, a2, a3, b0, b1);
        }
    }
}

#define DENSE_SMEM_BYTES (24576 + 8 * 4096)

__global__ void __launch_bounds__(256, 2)
k_dense(const float* __restrict__ Wv, const float* __restrict__ Bv,
        const float* __restrict__ Wt, const float* __restrict__ Bt) {
    extern __shared__ char sm[];
    int tower = blockIdx.y;
    const float* W = tower ? Wt : Wv;
    const float* Bb = tower ? Bt : Bv;
    int t = threadIdx.x;

    __half* Wsm = (__half*)sm;
    for (int idx = t; idx < 3 * 4096; idx += 256) {
        int m = idx >> 12;
        int n = (idx >> 6) & 63;
        int k = idx & 63;
        int chunk = (n >> 3) ^ (k & 7);
        Wsm[m * 4096 + k * 64 + chunk * 8 + (n & 7)] = __float2half_rn(W[idx]);
    }
    __syncthreads();

    int lane = t & 31, warp = t >> 5;
    char* bufX = sm + 24576 + warp * 4096;
    char* bufA = bufX + 2048;
    uint32_t uW = (uint32_t)__cvta_generic_to_shared(Wsm);
    uint32_t uX = (uint32_t)__cvta_generic_to_shared(bufX);
    uint32_t uA = (uint32_t)__cvta_generic_to_shared(bufA);

    const char* xg = (const char*)g_x + tower * 128;
    const char* ag = (const char*)g_agg + tower * 128;
    char* xo = (char*)g_x + tower * 128;

    const float* b0p = Bb;
    const float* b1p = Bb + 64;
    const float* b2p = Bb + 128;
    int cp = lane & 3;
    int rl = lane >> 2;
    int rlsw = rl & 7;

    for (int g = blockIdx.x * 8 + warp; g < NN / 16; g += gridDim.x * 8) {
        int rbase = g * 16;
#pragma unroll
        for (int i = 0; i < 4; i++) {
            int idx = i * 32 + lane;
            int r = idx >> 3, c = idx & 7;
            uint4 vx = *(const uint4*)(xg + (size_t)(rbase + r) * 256 + c * 16);
            uint4 va = *(const uint4*)(ag + (size_t)(rbase + r) * 256 + c * 16);
            int csw = c ^ (r & 7);
            *(uint4*)(bufX + r * 128 + csw * 16) = vx;
            *(uint4*)(bufA + r * 128 + csw * 16) = va;
        }
        __syncwarp();

        // ---- mv1: xh = leaky(x@W1^T + b1) + id
        float xh[32];
#pragma unroll
        for (int i = 0; i < 32; i++) xh[i] = 0.f;
        mv_mma(uX, uW + 8192, xh, lane);
        int row0 = rbase + rl;
#pragma unroll
        for (int j = 0; j < 8; j++) {
            float2 bb = ((const float2*)b1p)[j * 4 + cp];
            float2 i0 = __half22float2(g_idh[row0 * 32 + j * 4 + cp]);
            float2 i1 = __half22float2(g_idh[(row0 + 8) * 32 + j * 4 + cp]);
            xh[j * 4 + 0] = leaky(xh[j * 4 + 0] + bb.x) + i0.x;
            xh[j * 4 + 1] = leaky(xh[j * 4 + 1] + bb.y) + i0.y;
            xh[j * 4 + 2] = leaky(xh[j * 4 + 2] + bb.x) + i1.x;
            xh[j * 4 + 3] = leaky(xh[j * 4 + 3] + bb.y) + i1.y;
        }

        // ---- mv0: h = leaky(agg@W0^T + b0) -> fp16 restage into bufX
        float c2[32];
#pragma unroll
        for (int i = 0; i < 32; i++) c2[i] = 0.f;
        mv_mma(uA, uW, c2, lane);
        __syncwarp();
#pragma unroll
        for (int j = 0; j < 8; j++) {
            float2 bb = ((const float2*)b0p)[j * 4 + cp];
            __half2 h0 = __floats2half2_rn(leaky(c2[j * 4 + 0] + bb.x),
                                           leaky(c2[j * 4 + 1] + bb.y));
            __half2 h1 = __floats2half2_rn(leaky(c2[j * 4 + 2] + bb.x),
                                           leaky(c2[j * 4 + 3] + bb.y));
            int ch = (j ^ rlsw) << 4;
            *(__half2*)(bufX + rl * 128 + ch + cp * 4) = h0;
            *(__half2*)(bufX + (rl + 8) * 128 + ch + cp * 4) = h1;
        }
        __syncwarp();

        // ---- mv2: out = leaky(h@W2^T + b2 + xh)
#pragma unroll
        for (int j = 0; j < 8; j++) {
            float2 bb = ((const float2*)b2p)[j * 4 + cp];
            xh[j * 4 + 0] += bb.x;
            xh[j * 4 + 1] += bb.y;
            xh[j * 4 + 2] += bb.x;
            xh[j * 4 + 3] += bb.y;
        }
        mv_mma(uX, uW + 16384, xh, lane);
#pragma unroll
        for (int j = 0; j < 8; j++) {
            __half2 o0 = __floats2half2_rn(leaky(xh[j * 4 + 0]), leaky(xh[j * 4 + 1]));
            __half2 o1 = __floats2half2_rn(leaky(xh[j * 4 + 2]), leaky(xh[j * 4 + 3]));
            *(__half2*)(xo + (size_t)row0 * 256 + (j * 4 + cp) * 4) = o0;
            *(__half2*)(xo + (size_t)(row0 + 8) * 256 + (j * 4 + cp) * 4) = o1;
        }
    }
}

// ------------- final combine -------------------------------------------------
__global__ void k_combine(float2* __restrict__ out) {
    int i = blockIdx.x * blockDim.x + threadIdx.x;
    if (i < NN * 32) {
        int node = i >> 5, j = i & 31;
        float2 a = __half22float2(g_x[node * 64 + j]);
        float2 b = __half22float2(g_x[node * 64 + 32 + j]);
        out[i] = make_float2(0.5f * (a.x + b.x), 0.5f * (a.y + b.y));
    }
}

// ------------- launch --------------------------------------------------------
extern "C" void kernel_launch(void* const* d_in, const int* in_sizes, int n_in,
                              void* d_out, int out_size) {
    const float* v_feat = (const float*)d_in[0];
    const float* t_feat = (const float*)d_in[1];
    const float* id_emb = (const float*)d_in[2];
    const float* v_pref = (const float*)d_in[3];
    const float* t_pref = (const float*)d_in[4];
    const float* v_W    = (const float*)d_in[5];
    const float* v_b    = (const float*)d_in[6];
    const float* t_W    = (const float*)d_in[7];
    const float* t_b    = (const float*)d_in[8];
    const int*   edges  = (const int*)d_in[9];
    const int* row = edges;
    const int* col = edges + NE;
    float2* out = (float2*)d_out;

    void *degp, *statep;
    cudaGetSymbolAddress(&degp, g_deg);
    cudaGetSymbolAddress(&statep, g_state);

    static int attr_done = 0;
    if (!attr_done) {
        cudaFuncSetAttribute(k_dense, cudaFuncAttributeMaxDynamicSharedMemorySize,
                             DENSE_SMEM_BYTES);
        attr_done = 1;
    }

    cudaMemsetAsync(degp, 0, NN * sizeof(int));
    cudaMemsetAsync(statep, 0, NB_SCAN * sizeof(unsigned long long));

    k_init_hist<<<20000, 256>>>(v_pref, v_feat, t_pref, t_feat, id_emb, row);
    k_scan<<<NB_SCAN, 1024>>>();
    k_fill<<<(NE + 255) / 256, 256>>>(row, col);

    dim3 dgrid(148, 2);
    for (int layer = 0; layer < 2; layer++) {
        k_agg<<<2500, 512>>>();   // 40000 warps, 2 rows each
        k_dense<<<dgrid, 256, DENSE_SMEM_BYTES>>>(
            v_W + layer * 3 * 4096, v_b + layer * 3 * 64,
            t_W + layer * 3 * 4096, t_b + layer * 3 * 64);
    }

    k_combine<<<10000, 256>>>(out);
}

// round 14
// speedup vs baseline: 1.0859x; 1.0859x over previous
#include <cuda_runtime.h>
#include <cuda_fp16.h>
#include <cstdint>

#define NU 50000
#define NN 80000
#define NE 1600000
#define NB_SCAN 79   // ceil(80000/1024)
#define NCOL_PAD (NE + 7 * NN)

// ---------------- scratch (device globals; no allocation allowed) ----------
__device__ int    g_deg[NN];
__device__ int    g_off[NN + 1];      // PADDED offsets (multiples of 8)
__device__ int    g_cur[NN + 1];
__device__ unsigned long long g_state[NB_SCAN];
__device__ int    g_col[NCOL_PAD];
// interleaved feature storage: [node][towerA 32 half2][towerB 32 half2]
// row NN = dummy zero row (gather target for CSR padding)
__device__ __half2 g_x[(NN + 8) * 64];
__device__ __half2 g_agg[NN * 64];
__device__ __half2 g_idh[NN * 32];

__device__ __forceinline__ float leaky(float x) {
    return fmaxf(x, 0.01f * x);
}

__device__ __forceinline__ float2 add2(float2 a, float2 b) {
    unsigned long long ra = *reinterpret_cast<unsigned long long*>(&a);
    unsigned long long rb = *reinterpret_cast<unsigned long long*>(&b);
    unsigned long long rd;
    asm("add.rn.f32x2 %0, %1, %2;" : "=l"(rd) : "l"(ra), "l"(rb));
    return *reinterpret_cast<float2*>(&rd);
}

// ------------- launch 1: normalize + id->half + edge histogram --------------
__global__ void k_init_hist(const float* __restrict__ v_pref, const float* __restrict__ v_feat,
                            const float* __restrict__ t_pref, const float* __restrict__ t_feat,
                            const float* __restrict__ id_emb,
                            const int* __restrict__ row) {
    int gid = blockIdx.x * blockDim.x + threadIdx.x;
    if (gid < NE) atomicAdd(&g_deg[row[gid]], 1);
    if (gid < 64) g_x[NN * 64 + gid] = __float2half2_rn(0.f);   // dummy zero row
    int w = gid >> 5;
    int lane = gid & 31;
    if (w < NN) {
        float2 iv = ((const float2*)id_emb)[w * 32 + lane];
        g_idh[w * 32 + lane] = __float22half2_rn(iv);
    }
    if (w >= 2 * NN) return;
    int tower = (w >= NN) ? 1 : 0;
    int n = w - tower * NN;
    const float2* src;
    if (tower == 0)
        src = (n < NU) ? (const float2*)v_pref + n * 32 : (const float2*)v_feat + (n - NU) * 32;
    else
        src = (n < NU) ? (const float2*)t_pref + n * 32 : (const float2*)t_feat + (n - NU) * 32;
    float2 v = src[lane];
    float ss = v.x * v.x + v.y * v.y;
#pragma unroll
    for (int o = 16; o > 0; o >>= 1) ss += __shfl_xor_sync(0xffffffffu, ss, o);
    float inv = 1.0f / fmaxf(sqrtf(ss), 1e-12f);
    g_x[n * 64 + tower * 32 + lane] = __float22half2_rn(make_float2(v.x * inv, v.y * inv));
}

// ------------- launch 2: scan of PADDED degrees + pad-slot fill --------------
__global__ void k_scan() {
    __shared__ int s[1024];
    __shared__ int s_prev;
    int tid = threadIdx.x;
    int i = blockIdx.x * 1024 + tid;
    int dv = (i < NN) ? g_deg[i] : 0;
    int v = (dv + 7) & ~7;             // padded degree
    s[tid] = v;
    __syncthreads();
#pragma unroll
    for (int off = 1; off < 1024; off <<= 1) {
        int t = (tid >= off) ? s[tid - off] : 0;
        __syncthreads();
        s[tid] += t;
        __syncthreads();
    }
    if (tid == 0) {
        unsigned long long mine = (1ULL << 32) | (unsigned)s[1023];
        atomicExch(&g_state[blockIdx.x], mine);
    }
    if (tid < 32) {
        int sum = 0;
        for (int j = tid; j < blockIdx.x; j += 32) {
            unsigned long long st;
            do { st = atomicAdd(&g_state[j], 0ULL); } while (!(st >> 32));
            sum += (int)(unsigned)st;
        }
#pragma unroll
        for (int o = 16; o > 0; o >>= 1) sum += __shfl_xor_sync(0xffffffffu, sum, o);
        if (tid == 0) s_prev = sum;
    }
    __syncthreads();
    int val = s[tid] + s_prev;          // inclusive padded offset (= off[i+1])
    if (i < NN) {
        g_off[i + 1] = val;
        g_cur[i + 1] = val;
        for (int p = val - (v - dv); p < val; p++) g_col[p] = NN;
    }
    if (i == 0) { g_off[0] = 0; g_cur[0] = 0; }
}

// ------------- launch 3: CSR fill -------------------------------------------
__global__ void k_fill(const int* __restrict__ row, const int* __restrict__ col) {
    int e = blockIdx.x * blockDim.x + threadIdx.x;
    if (e < NE) {
        int r = row[e];
        int p = atomicAdd(&g_cur[r], 1);
        g_col[p] = col[e];
    }
}

// ------------- aggregation: warp per row, both towers, pipelined col loads ---
__device__ __forceinline__ void quadAB(const char* xb, int4 c, float2& A, float2& B) {
    const char* p0 = xb + ((unsigned)c.x << 8);
    const char* p1 = xb + ((unsigned)c.y << 8);
    const char* p2 = xb + ((unsigned)c.z << 8);
    const char* p3 = xb + ((unsigned)c.w << 8);
    __half2 a0 = *(const __half2*)p0;
    __half2 a1 = *(const __half2*)p1;
    __half2 a2 = *(const __half2*)p2;
    __half2 a3 = *(const __half2*)p3;
    __half2 b0 = *(const __half2*)(p0 + 128);
    __half2 b1 = *(const __half2*)(p1 + 128);
    __half2 b2 = *(const __half2*)(p2 + 128);
    __half2 b3 = *(const __half2*)(p3 + 128);
    __half2 qA = __hadd2(__hadd2(a0, a1), __hadd2(a2, a3));
    __half2 qB = __hadd2(__hadd2(b0, b1), __hadd2(b2, b3));
    A = add2(A, __half22float2(qA));
    B = add2(B, __half22float2(qB));
}

__global__ void __launch_bounds__(512)
k_agg() {
    int r = (blockIdx.x * 512 + threadIdx.x) >> 5;
    if (r >= NN) return;
    int lane = threadIdx.x & 31;
    const char* xb = (const char*)g_x + lane * 4;
    int beg = g_off[r], end = g_off[r + 1];      // end-beg multiple of 8, >= 8
    float2 A = {0.f, 0.f}, B = {0.f, 0.f};

    int e = beg;
    int4 ca = *(const int4*)(g_col + e);
    int4 cb = *(const int4*)(g_col + e + 4);
    while (e + 8 < end) {
        // prefetch next oct's col vectors (hides col-load latency)
        int4 na = *(const int4*)(g_col + e + 8);
        int4 nb = *(const int4*)(g_col + e + 12);
        quadAB(xb, ca, A, B);
        quadAB(xb, cb, A, B);
        ca = na; cb = nb;
        e += 8;
    }
    quadAB(xb, ca, A, B);
    quadAB(xb, cb, A, B);

    float invd = __fdividef(1.0f, (float)g_deg[r]);
    g_agg[r * 64 + lane]      = __float22half2_rn(make_float2(A.x * invd, A.y * invd));
    g_agg[r * 64 + 32 + lane] = __float22half2_rn(make_float2(B.x * invd, B.y * invd));
}

// ------------- dense via tensor cores (mma.sync m16n8k16 f16->f32) ----------
__device__ __forceinline__ void ldmA(uint32_t addr, uint32_t& a0, uint32_t& a1,
                                     uint32_t& a2, uint32_t& a3) {
    asm volatile("ldmatrix.sync.aligned.m8n8.x4.shared.b16 {%0,%1,%2,%3}, [%4];"
                 : "=r"(a0), "=r"(a1), "=r"(a2), "=r"(a3) : "r"(addr));
}
__device__ __forceinline__ void ldmB(uint32_t addr, uint32_t& b0, uint32_t& b1) {
    asm volatile("ldmatrix.sync.aligned.m8n8.x2.trans.shared.b16 {%0,%1}, [%2];"
                 : "=r"(b0), "=r"(b1) : "r"(addr));
}
__device__ __forceinline__ void hmma(float& c0, float& c1, float& c2, float& c3,
                                     uint32_t a0, uint32_t a1, uint32_t a2, uint32_t a3,
                                     uint32_t b0, uint32_t b1) {
    asm volatile("mma.sync.aligned.m16n8k16.row.col.f32.f16.f16.f32 "
                 "{%0,%1,%2,%3}, {%4,%5,%6,%7}, {%8,%9}, {%0,%1,%2,%3};"
                 : "+f"(c0), "+f"(c1), "+f"(c2), "+f"(c3)
                 : "r"(a0), "r"(a1), "r"(a2), "r"(a3), "r"(b0), "r"(b1));
}

__device__ __forceinline__ void mv_mma(uint32_t uA, uint32_t uWm, float* c, int lane) {
    int r = lane & 15;
    int hiA = lane >> 4;
    int rsw = r & 7;
#pragma unroll
    for (int s = 0; s < 4; s++) {
        uint32_t a0, a1, a2, a3;
        ldmA(uA + r * 128 + (((2 * s + hiA) ^ rsw) << 4), a0, a1, a2, a3);
        uint32_t rowB = uWm + (16 * s + r) * 128;
#pragma unroll
        for (int j = 0; j < 8; j++) {
            uint32_t b0, b1;
            ldmB(rowB + ((j ^ rsw) << 4), b0, b1);
            hmma(c[j * 4], c[j * 4 + 1], c[j * 4 + 2], c[j * 4 + 3],
                 a0, a1, a2, a3, b0, b1);
        }
    }
}

#define DENSE_SMEM_BYTES (24576 + 8 * 4096)

__global__ void __launch_bounds__(256, 2)
k_dense(const float* __restrict__ Wv, const float* __restrict__ Bv,
        const float* __restrict__ Wt, const float* __restrict__ Bt) {
    extern __shared__ char sm[];
    int tower = blockIdx.y;
    const float* W = tower ? Wt : Wv;
    const float* Bb = tower ? Bt : Bv;
    int t = threadIdx.x;

    __half* Wsm = (__half*)sm;
    for (int idx = t; idx < 3 * 4096; idx += 256) {
        int m = idx >> 12;
        int n = (idx >> 6) & 63;
        int k = idx & 63;
        int chunk = (n >> 3) ^ (k & 7);
        Wsm[m * 4096 + k * 64 + chunk * 8 + (n & 7)] = __float2half_rn(W[idx]);
    }
    __syncthreads();

    int lane = t & 31, warp = t >> 5;
    char* bufX = sm + 24576 + warp * 4096;
    char* bufA = bufX + 2048;
    uint32_t uW = (uint32_t)__cvta_generic_to_shared(Wsm);
    uint32_t uX = (uint32_t)__cvta_generic_to_shared(bufX);
    uint32_t uA = (uint32_t)__cvta_generic_to_shared(bufA);

    const char* xg = (const char*)g_x + tower * 128;
    const char* ag = (const char*)g_agg + tower * 128;
    char* xo = (char*)g_x + tower * 128;

    const float* b0p = Bb;
    const float* b1p = Bb + 64;
    const float* b2p = Bb + 128;
    int cp = lane & 3;
    int rl = lane >> 2;
    int rlsw = rl & 7;

    for (int g = blockIdx.x * 8 + warp; g < NN / 16; g += gridDim.x * 8) {
        int rbase = g * 16;
#pragma unroll
        for (int i = 0; i < 4; i++) {
            int idx = i * 32 + lane;
            int r = idx >> 3, c = idx & 7;
            uint4 vx = *(const uint4*)(xg + (size_t)(rbase + r) * 256 + c * 16);
            uint4 va = *(const uint4*)(ag + (size_t)(rbase + r) * 256 + c * 16);
            int csw = c ^ (r & 7);
            *(uint4*)(bufX + r * 128 + csw * 16) = vx;
            *(uint4*)(bufA + r * 128 + csw * 16) = va;
        }
        __syncwarp();

        // ---- mv1: xh = leaky(x@W1^T + b1) + id
        float xh[32];
#pragma unroll
        for (int i = 0; i < 32; i++) xh[i] = 0.f;
        mv_mma(uX, uW + 8192, xh, lane);
        int row0 = rbase + rl;
#pragma unroll
        for (int j = 0; j < 8; j++) {
            float2 bb = ((const float2*)b1p)[j * 4 + cp];
            float2 i0 = __half22float2(g_idh[row0 * 32 + j * 4 + cp]);
            float2 i1 = __half22float2(g_idh[(row0 + 8) * 32 + j * 4 + cp]);
            xh[j * 4 + 0] = leaky(xh[j * 4 + 0] + bb.x) + i0.x;
            xh[j * 4 + 1] = leaky(xh[j * 4 + 1] + bb.y) + i0.y;
            xh[j * 4 + 2] = leaky(xh[j * 4 + 2] + bb.x) + i1.x;
            xh[j * 4 + 3] = leaky(xh[j * 4 + 3] + bb.y) + i1.y;
        }

        // ---- mv0: h = leaky(agg@W0^T + b0) -> fp16 restage into bufX
        float c2[32];
#pragma unroll
        for (int i = 0; i < 32; i++) c2[i] = 0.f;
        mv_mma(uA, uW, c2, lane);
        __syncwarp();
#pragma unroll
        for (int j = 0; j < 8; j++) {
            float2 bb = ((const float2*)b0p)[j * 4 + cp];
            __half2 h0 = __floats2half2_rn(leaky(c2[j * 4 + 0] + bb.x),
                                           leaky(c2[j * 4 + 1] + bb.y));
            __half2 h1 = __floats2half2_rn(leaky(c2[j * 4 + 2] + bb.x),
                                           leaky(c2[j * 4 + 3] + bb.y));
            int ch = (j ^ rlsw) << 4;
            *(__half2*)(bufX + rl * 128 + ch + cp * 4) = h0;
            *(__half2*)(bufX + (rl + 8) * 128 + ch + cp * 4) = h1;
        }
        __syncwarp();

        // ---- mv2: out = leaky(h@W2^T + b2 + xh)
#pragma unroll
        for (int j = 0; j < 8; j++) {
            float2 bb = ((const float2*)b2p)[j * 4 + cp];
            xh[j * 4 + 0] += bb.x;
            xh[j * 4 + 1] += bb.y;
            xh[j * 4 + 2] += bb.x;
            xh[j * 4 + 3] += bb.y;
        }
        mv_mma(uX, uW + 16384, xh, lane);
#pragma unroll
        for (int j = 0; j < 8; j++) {
            __half2 o0 = __floats2half2_rn(leaky(xh[j * 4 + 0]), leaky(xh[j * 4 + 1]));
            __half2 o1 = __floats2half2_rn(leaky(xh[j * 4 + 2]), leaky(xh[j * 4 + 3]));
            *(__half2*)(xo + (size_t)row0 * 256 + (j * 4 + cp) * 4) = o0;
            *(__half2*)(xo + (size_t)(row0 + 8) * 256 + (j * 4 + cp) * 4) = o1;
        }
    }
}

// ------------- final combine -------------------------------------------------
__global__ void k_combine(float2* __restrict__ out) {
    int i = blockIdx.x * blockDim.x + threadIdx.x;
    if (i < NN * 32) {
        int node = i >> 5, j = i & 31;
        float2 a = __half22float2(g_x[node * 64 + j]);
        float2 b = __half22float2(g_x[node * 64 + 32 + j]);
        out[i] = make_float2(0.5f * (a.x + b.x), 0.5f * (a.y + b.y));
    }
}

// ------------- launch --------------------------------------------------------
extern "C" void kernel_launch(void* const* d_in, const int* in_sizes, int n_in,
                              void* d_out, int out_size) {
    const float* v_feat = (const float*)d_in[0];
    const float* t_feat = (const float*)d_in[1];
    const float* id_emb = (const float*)d_in[2];
    const float* v_pref = (const float*)d_in[3];
    const float* t_pref = (const float*)d_in[4];
    const float* v_W    = (const float*)d_in[5];
    const float* v_b    = (const float*)d_in[6];
    const float* t_W    = (const float*)d_in[7];
    const float* t_b    = (const float*)d_in[8];
    const int*   edges  = (const int*)d_in[9];
    const int* row = edges;
    const int* col = edges + NE;
    float2* out = (float2*)d_out;

    void *degp, *statep;
    cudaGetSymbolAddress(&degp, g_deg);
    cudaGetSymbolAddress(&statep, g_state);

    static int attr_done = 0;
    if (!attr_done) {
        cudaFuncSetAttribute(k_dense, cudaFuncAttributeMaxDynamicSharedMemorySize,
                             DENSE_SMEM_BYTES);
        attr_done = 1;
    }

    cudaMemsetAsync(degp, 0, NN * sizeof(int));
    cudaMemsetAsync(statep, 0, NB_SCAN * sizeof(unsigned long long));

    k_init_hist<<<20000, 256>>>(v_pref, v_feat, t_pref, t_feat, id_emb, row);
    k_scan<<<NB_SCAN, 1024>>>();
    k_fill<<<(NE + 255) / 256, 256>>>(row, col);

    dim3 dgrid(148, 2);
    for (int layer = 0; layer < 2; layer++) {
        k_agg<<<5000, 512>>>();   // warp per row (R11-proven shape)
        k_dense<<<dgrid, 256, DENSE_SMEM_BYTES>>>(
            v_W + layer * 3 * 4096, v_b + layer * 3 * 64,
            t_W + layer * 3 * 4096, t_b + layer * 3 * 64);
    }

    k_combine<<<10000, 256>>>(out);
}

// round 15
// speedup vs baseline: 1.1271x; 1.0380x over previous
#include <cuda_runtime.h>
#include <cuda_fp16.h>
#include <cstdint>

#define NU 50000
#define NN 80000
#define NE 1600000
#define NB_SCAN 79   // ceil(80000/1024)
#define NCOL_PAD (NE + 7 * NN)

// ---------------- scratch (device globals; no allocation allowed) ----------
__device__ int    g_deg[NN];
__device__ int    g_off[NN + 1];      // PADDED offsets (multiples of 8)
__device__ int    g_cur[NN + 1];
__device__ unsigned long long g_state[NB_SCAN];
__device__ int    g_col[NCOL_PAD];    // PREMULTIPLIED byte offsets (col * 256)
// interleaved feature storage: [node][towerA 32 half2][towerB 32 half2]
// row NN = dummy zero row (gather target for CSR padding)
__device__ __half2 g_x[(NN + 8) * 64];
__device__ __half2 g_agg[NN * 64];
__device__ __half2 g_idh[NN * 32];

__device__ __forceinline__ float leaky(float x) {
    return fmaxf(x, 0.01f * x);
}

__device__ __forceinline__ float2 add2(float2 a, float2 b) {
    unsigned long long ra = *reinterpret_cast<unsigned long long*>(&a);
    unsigned long long rb = *reinterpret_cast<unsigned long long*>(&b);
    unsigned long long rd;
    asm("add.rn.f32x2 %0, %1, %2;" : "=l"(rd) : "l"(ra), "l"(rb));
    return *reinterpret_cast<float2*>(&rd);
}

// ------------- launch 1: normalize + id->half + edge histogram --------------
__global__ void k_init_hist(const float* __restrict__ v_pref, const float* __restrict__ v_feat,
                            const float* __restrict__ t_pref, const float* __restrict__ t_feat,
                            const float* __restrict__ id_emb,
                            const int* __restrict__ row) {
    int gid = blockIdx.x * blockDim.x + threadIdx.x;
    if (gid < NE) atomicAdd(&g_deg[row[gid]], 1);
    if (gid < 64) g_x[NN * 64 + gid] = __float2half2_rn(0.f);   // dummy zero row
    int w = gid >> 5;
    int lane = gid & 31;
    if (w < NN) {
        float2 iv = ((const float2*)id_emb)[w * 32 + lane];
        g_idh[w * 32 + lane] = __float22half2_rn(iv);
    }
    if (w >= 2 * NN) return;
    int tower = (w >= NN) ? 1 : 0;
    int n = w - tower * NN;
    const float2* src;
    if (tower == 0)
        src = (n < NU) ? (const float2*)v_pref + n * 32 : (const float2*)v_feat + (n - NU) * 32;
    else
        src = (n < NU) ? (const float2*)t_pref + n * 32 : (const float2*)t_feat + (n - NU) * 32;
    float2 v = src[lane];
    float ss = v.x * v.x + v.y * v.y;
#pragma unroll
    for (int o = 16; o > 0; o >>= 1) ss += __shfl_xor_sync(0xffffffffu, ss, o);
    float inv = 1.0f / fmaxf(sqrtf(ss), 1e-12f);
    g_x[n * 64 + tower * 32 + lane] = __float22half2_rn(make_float2(v.x * inv, v.y * inv));
}

// ------------- launch 2: scan of PADDED degrees + pad-slot fill --------------
__global__ void k_scan() {
    __shared__ int s[1024];
    __shared__ int s_prev;
    int tid = threadIdx.x;
    int i = blockIdx.x * 1024 + tid;
    int dv = (i < NN) ? g_deg[i] : 0;
    int v = (dv + 7) & ~7;             // padded degree
    s[tid] = v;
    __syncthreads();
#pragma unroll
    for (int off = 1; off < 1024; off <<= 1) {
        int t = (tid >= off) ? s[tid - off] : 0;
        __syncthreads();
        s[tid] += t;
        __syncthreads();
    }
    if (tid == 0) {
        unsigned long long mine = (1ULL << 32) | (unsigned)s[1023];
        atomicExch(&g_state[blockIdx.x], mine);
    }
    if (tid < 32) {
        int sum = 0;
        for (int j = tid; j < blockIdx.x; j += 32) {
            unsigned long long st;
            do { st = atomicAdd(&g_state[j], 0ULL); } while (!(st >> 32));
            sum += (int)(unsigned)st;
        }
#pragma unroll
        for (int o = 16; o > 0; o >>= 1) sum += __shfl_xor_sync(0xffffffffu, sum, o);
        if (tid == 0) s_prev = sum;
    }
    __syncthreads();
    int val = s[tid] + s_prev;          // inclusive padded offset (= off[i+1])
    if (i < NN) {
        g_off[i + 1] = val;
        g_cur[i + 1] = val;
        for (int p = val - (v - dv); p < val; p++) g_col[p] = NN * 256;  // pad -> zero row
    }
    if (i == 0) { g_off[0] = 0; g_cur[0] = 0; }
}

// ------------- launch 3: CSR fill (stores premultiplied byte offsets) -------
__global__ void k_fill(const int* __restrict__ row, const int* __restrict__ col) {
    int e = blockIdx.x * blockDim.x + threadIdx.x;
    if (e < NE) {
        int r = row[e];
        int p = atomicAdd(&g_cur[r], 1);
        g_col[p] = col[e] << 8;
    }
}

// ------------- aggregation: warp per row, both towers (R11 shape) ------------
__device__ __forceinline__ void quadAB(const char* xb, int4 c, float2& A, float2& B) {
    const char* p0 = xb + (unsigned)c.x;
    const char* p1 = xb + (unsigned)c.y;
    const char* p2 = xb + (unsigned)c.z;
    const char* p3 = xb + (unsigned)c.w;
    __half2 a0 = *(const __half2*)p0;
    __half2 a1 = *(const __half2*)p1;
    __half2 a2 = *(const __half2*)p2;
    __half2 a3 = *(const __half2*)p3;
    __half2 b0 = *(const __half2*)(p0 + 128);
    __half2 b1 = *(const __half2*)(p1 + 128);
    __half2 b2 = *(const __half2*)(p2 + 128);
    __half2 b3 = *(const __half2*)(p3 + 128);
    __half2 qA = __hadd2(__hadd2(a0, a1), __hadd2(a2, a3));
    __half2 qB = __hadd2(__hadd2(b0, b1), __hadd2(b2, b3));
    A = add2(A, __half22float2(qA));
    B = add2(B, __half22float2(qB));
}

__global__ void __launch_bounds__(512)
k_agg() {
    int r = (blockIdx.x * 512 + threadIdx.x) >> 5;
    if (r >= NN) return;
    int lane = threadIdx.x & 31;
    const char* xb = (const char*)g_x + lane * 4;
    int beg = g_off[r], end = g_off[r + 1];      // multiple of 8 edges
    float2 A = {0.f, 0.f}, B = {0.f, 0.f};
    for (int e = beg; e < end; e += 8) {
        int4 ca = *(const int4*)(g_col + e);
        int4 cb = *(const int4*)(g_col + e + 4);
        quadAB(xb, ca, A, B);
        quadAB(xb, cb, A, B);
    }
    float invd = __fdividef(1.0f, (float)g_deg[r]);
    g_agg[r * 64 + lane]      = __float22half2_rn(make_float2(A.x * invd, A.y * invd));
    g_agg[r * 64 + 32 + lane] = __float22half2_rn(make_float2(B.x * invd, B.y * invd));
}

// ------------- dense via tensor cores (mma.sync m16n8k16 f16->f32) ----------
__device__ __forceinline__ void ldmA(uint32_t addr, uint32_t& a0, uint32_t& a1,
                                     uint32_t& a2, uint32_t& a3) {
    asm volatile("ldmatrix.sync.aligned.m8n8.x4.shared.b16 {%0,%1,%2,%3}, [%4];"
                 : "=r"(a0), "=r"(a1), "=r"(a2), "=r"(a3) : "r"(addr));
}
__device__ __forceinline__ void ldmB(uint32_t addr, uint32_t& b0, uint32_t& b1) {
    asm volatile("ldmatrix.sync.aligned.m8n8.x2.trans.shared.b16 {%0,%1}, [%2];"
                 : "=r"(b0), "=r"(b1) : "r"(addr));
}
__device__ __forceinline__ void hmma(float& c0, float& c1, float& c2, float& c3,
                                     uint32_t a0, uint32_t a1, uint32_t a2, uint32_t a3,
                                     uint32_t b0, uint32_t b1) {
    asm volatile("mma.sync.aligned.m16n8k16.row.col.f32.f16.f16.f32 "
                 "{%0,%1,%2,%3}, {%4,%5,%6,%7}, {%8,%9}, {%0,%1,%2,%3};"
                 : "+f"(c0), "+f"(c1), "+f"(c2), "+f"(c3)
                 : "r"(a0), "r"(a1), "r"(a2), "r"(a3), "r"(b0), "r"(b1));
}

__device__ __forceinline__ void mv_mma(uint32_t uA, uint32_t uWm, float* c, int lane) {
    int r = lane & 15;
    int hiA = lane >> 4;
    int rsw = r & 7;
#pragma unroll
    for (int s = 0; s < 4; s++) {
        uint32_t a0, a1, a2, a3;
        ldmA(uA + r * 128 + (((2 * s + hiA) ^ rsw) << 4), a0, a1, a2, a3);
        uint32_t rowB = uWm + (16 * s + r) * 128;
#pragma unroll
        for (int j = 0; j < 8; j++) {
            uint32_t b0, b1;
            ldmB(rowB + ((j ^ rsw) << 4), b0, b1);
            hmma(c[j * 4], c[j * 4 + 1], c[j * 4 + 2], c[j * 4 + 3],
                 a0, a1, a2, a3, b0, b1);
        }
    }
}

#define DENSE_SMEM_BYTES (24576 + 8 * 4096)

__global__ void __launch_bounds__(256, 2)
k_dense(const float* __restrict__ Wv, const float* __restrict__ Bv,
        const float* __restrict__ Wt, const float* __restrict__ Bt) {
    extern __shared__ char sm[];
    int tower = blockIdx.y;
    const float* W = tower ? Wt : Wv;
    const float* Bb = tower ? Bt : Bv;
    int t = threadIdx.x;

    __half* Wsm = (__half*)sm;
    for (int idx = t; idx < 3 * 4096; idx += 256) {
        int m = idx >> 12;
        int n = (idx >> 6) & 63;
        int k = idx & 63;
        int chunk = (n >> 3) ^ (k & 7);
        Wsm[m * 4096 + k * 64 + chunk * 8 + (n & 7)] = __float2half_rn(W[idx]);
    }
    __syncthreads();

    int lane = t & 31, warp = t >> 5;
    char* bufX = sm + 24576 + warp * 4096;
    char* bufA = bufX + 2048;
    uint32_t uW = (uint32_t)__cvta_generic_to_shared(Wsm);
    uint32_t uX = (uint32_t)__cvta_generic_to_shared(bufX);
    uint32_t uA = (uint32_t)__cvta_generic_to_shared(bufA);

    const char* xg = (const char*)g_x + tower * 128;
    const char* ag = (const char*)g_agg + tower * 128;
    char* xo = (char*)g_x + tower * 128;

    const float* b0p = Bb;
    const float* b1p = Bb + 64;
    const float* b2p = Bb + 128;
    int cp = lane & 3;
    int rl = lane >> 2;
    int rlsw = rl & 7;

    for (int g = blockIdx.x * 8 + warp; g < NN / 16; g += gridDim.x * 8) {
        int rbase = g * 16;
#pragma unroll
        for (int i = 0; i < 4; i++) {
            int idx = i * 32 + lane;
            int r = idx >> 3, c = idx & 7;
            uint4 vx = *(const uint4*)(xg + (size_t)(rbase + r) * 256 + c * 16);
            uint4 va = *(const uint4*)(ag + (size_t)(rbase + r) * 256 + c * 16);
            int csw = c ^ (r & 7);
            *(uint4*)(bufX + r * 128 + csw * 16) = vx;
            *(uint4*)(bufA + r * 128 + csw * 16) = va;
        }
        __syncwarp();

        // ---- mv1: xh = leaky(x@W1^T + b1) + id
        float xh[32];
#pragma unroll
        for (int i = 0; i < 32; i++) xh[i] = 0.f;
        mv_mma(uX, uW + 8192, xh, lane);
        int row0 = rbase + rl;
#pragma unroll
        for (int j = 0; j < 8; j++) {
            float2 bb = ((const float2*)b1p)[j * 4 + cp];
            float2 i0 = __half22float2(g_idh[row0 * 32 + j * 4 + cp]);
            float2 i1 = __half22float2(g_idh[(row0 + 8) * 32 + j * 4 + cp]);
            xh[j * 4 + 0] = leaky(xh[j * 4 + 0] + bb.x) + i0.x;
            xh[j * 4 + 1] = leaky(xh[j * 4 + 1] + bb.y) + i0.y;
            xh[j * 4 + 2] = leaky(xh[j * 4 + 2] + bb.x) + i1.x;
            xh[j * 4 + 3] = leaky(xh[j * 4 + 3] + bb.y) + i1.y;
        }

        // ---- mv0: h = leaky(agg@W0^T + b0) -> fp16 restage into bufX
        float c2[32];
#pragma unroll
        for (int i = 0; i < 32; i++) c2[i] = 0.f;
        mv_mma(uA, uW, c2, lane);
        __syncwarp();
#pragma unroll
        for (int j = 0; j < 8; j++) {
            float2 bb = ((const float2*)b0p)[j * 4 + cp];
            __half2 h0 = __floats2half2_rn(leaky(c2[j * 4 + 0] + bb.x),
                                           leaky(c2[j * 4 + 1] + bb.y));
            __half2 h1 = __floats2half2_rn(leaky(c2[j * 4 + 2] + bb.x),
                                           leaky(c2[j * 4 + 3] + bb.y));
            int ch = (j ^ rlsw) << 4;
            *(__half2*)(bufX + rl * 128 + ch + cp * 4) = h0;
            *(__half2*)(bufX + (rl + 8) * 128 + ch + cp * 4) = h1;
        }
        __syncwarp();

        // ---- mv2: out = leaky(h@W2^T + b2 + xh)
#pragma unroll
        for (int j = 0; j < 8; j++) {
            float2 bb = ((const float2*)b2p)[j * 4 + cp];
            xh[j * 4 + 0] += bb.x;
            xh[j * 4 + 1] += bb.y;
            xh[j * 4 + 2] += bb.x;
            xh[j * 4 + 3] += bb.y;
        }
        mv_mma(uX, uW + 16384, xh, lane);
#pragma unroll
        for (int j = 0; j < 8; j++) {
            __half2 o0 = __floats2half2_rn(leaky(xh[j * 4 + 0]), leaky(xh[j * 4 + 1]));
            __half2 o1 = __floats2half2_rn(leaky(xh[j * 4 + 2]), leaky(xh[j * 4 + 3]));
            *(__half2*)(xo + (size_t)row0 * 256 + (j * 4 + cp) * 4) = o0;
            *(__half2*)(xo + (size_t)(row0 + 8) * 256 + (j * 4 + cp) * 4) = o1;
        }
    }
}

// ------------- final combine -------------------------------------------------
__global__ void k_combine(float2* __restrict__ out) {
    int i = blockIdx.x * blockDim.x + threadIdx.x;
    if (i < NN * 32) {
        int node = i >> 5, j = i & 31;
        float2 a = __half22float2(g_x[node * 64 + j]);
        float2 b = __half22float2(g_x[node * 64 + 32 + j]);
        out[i] = make_float2(0.5f * (a.x + b.x), 0.5f * (a.y + b.y));
    }
}

// ------------- launch --------------------------------------------------------
extern "C" void kernel_launch(void* const* d_in, const int* in_sizes, int n_in,
                              void* d_out, int out_size) {
    const float* v_feat = (const float*)d_in[0];
    const float* t_feat = (const float*)d_in[1];
    const float* id_emb = (const float*)d_in[2];
    const float* v_pref = (const float*)d_in[3];
    const float* t_pref = (const float*)d_in[4];
    const float* v_W    = (const float*)d_in[5];
    const float* v_b    = (const float*)d_in[6];
    const float* t_W    = (const float*)d_in[7];
    const float* t_b    = (const float*)d_in[8];
    const int*   edges  = (const int*)d_in[9];
    const int* row = edges;
    const int* col = edges + NE;
    float2* out = (float2*)d_out;

    void *degp, *statep;
    cudaGetSymbolAddress(&degp, g_deg);
    cudaGetSymbolAddress(&statep, g_state);

    static int attr_done = 0;
    if (!attr_done) {
        cudaFuncSetAttribute(k_dense, cudaFuncAttributeMaxDynamicSharedMemorySize,
                             DENSE_SMEM_BYTES);
        attr_done = 1;
    }

    cudaMemsetAsync(degp, 0, NN * sizeof(int));
    cudaMemsetAsync(statep, 0, NB_SCAN * sizeof(unsigned long long));

    k_init_hist<<<20000, 256>>>(v_pref, v_feat, t_pref, t_feat, id_emb, row);
    k_scan<<<NB_SCAN, 1024>>>();
    k_fill<<<(NE + 255) / 256, 256>>>(row, col);

    dim3 dgrid(148, 2);
    for (int layer = 0; layer < 2; layer++) {
        k_agg<<<5000, 512>>>();   // warp per row (R11-proven shape)
        k_dense<<<dgrid, 256, DENSE_SMEM_BYTES>>>(
            v_W + layer * 3 * 4096, v_b + layer * 3 * 64,
            t_W + layer * 3 * 4096, t_b + layer * 3 * 64);
    }

    k_combine<<<10000, 256>>>(out);
}

// round 16
// speedup vs baseline: 1.1383x; 1.0099x over previous
#include <cuda_runtime.h>
#include <cuda_fp16.h>
#include <cstdint>

#define NU 50000
#define NN 80000
#define NE 1600000
#define NB_SCAN 79   // ceil(80000/1024)
#define NCOL_PAD (NE + 7 * NN)

// ---------------- scratch (device globals; no allocation allowed) ----------
__device__ int    g_deg[NN];
__device__ int    g_off[NN + 1];      // PADDED offsets (multiples of 8)
__device__ int    g_rank[NE];         // edge rank within its row (from hist atomic)
__device__ unsigned long long g_state[NB_SCAN];
__device__ int    g_col[NCOL_PAD];    // PREMULTIPLIED byte offsets (col * 256)
// interleaved feature storage: [node][towerA 32 half2][towerB 32 half2]
// row NN = dummy zero row (gather target for CSR padding)
__device__ __half2 g_x[(NN + 8) * 64];
__device__ __half2 g_agg[NN * 64];
__device__ __half2 g_idh[NN * 32];

__device__ __forceinline__ float leaky(float x) {
    return fmaxf(x, 0.01f * x);
}

__device__ __forceinline__ float2 add2(float2 a, float2 b) {
    unsigned long long ra = *reinterpret_cast<unsigned long long*>(&a);
    unsigned long long rb = *reinterpret_cast<unsigned long long*>(&b);
    unsigned long long rd;
    asm("add.rn.f32x2 %0, %1, %2;" : "=l"(rd) : "l"(ra), "l"(rb));
    return *reinterpret_cast<float2*>(&rd);
}

// ------------- launch 1: normalize + id->half + edge histogram (rank) -------
__global__ void k_init_hist(const float* __restrict__ v_pref, const float* __restrict__ v_feat,
                            const float* __restrict__ t_pref, const float* __restrict__ t_feat,
                            const float* __restrict__ id_emb,
                            const int* __restrict__ row) {
    int gid = blockIdx.x * blockDim.x + threadIdx.x;
    if (gid < NE) g_rank[gid] = atomicAdd(&g_deg[row[gid]], 1);  // rank = old count
    if (gid < 64) g_x[NN * 64 + gid] = __float2half2_rn(0.f);    // dummy zero row
    int w = gid >> 5;
    int lane = gid & 31;
    if (w < NN) {
        float2 iv = ((const float2*)id_emb)[w * 32 + lane];
        g_idh[w * 32 + lane] = __float22half2_rn(iv);
    }
    if (w >= 2 * NN) return;
    int tower = (w >= NN) ? 1 : 0;
    int n = w - tower * NN;
    const float2* src;
    if (tower == 0)
        src = (n < NU) ? (const float2*)v_pref + n * 32 : (const float2*)v_feat + (n - NU) * 32;
    else
        src = (n < NU) ? (const float2*)t_pref + n * 32 : (const float2*)t_feat + (n - NU) * 32;
    float2 v = src[lane];
    float ss = v.x * v.x + v.y * v.y;
#pragma unroll
    for (int o = 16; o > 0; o >>= 1) ss += __shfl_xor_sync(0xffffffffu, ss, o);
    float inv = 1.0f / fmaxf(sqrtf(ss), 1e-12f);
    g_x[n * 64 + tower * 32 + lane] = __float22half2_rn(make_float2(v.x * inv, v.y * inv));
}

// ------------- launch 2: scan of PADDED degrees + pad-slot fill --------------
__global__ void k_scan() {
    __shared__ int s[1024];
    __shared__ int s_prev;
    int tid = threadIdx.x;
    int i = blockIdx.x * 1024 + tid;
    int dv = (i < NN) ? g_deg[i] : 0;
    int v = (dv + 7) & ~7;             // padded degree
    s[tid] = v;
    __syncthreads();
#pragma unroll
    for (int off = 1; off < 1024; off <<= 1) {
        int t = (tid >= off) ? s[tid - off] : 0;
        __syncthreads();
        s[tid] += t;
        __syncthreads();
    }
    if (tid == 0) {
        unsigned long long mine = (1ULL << 32) | (unsigned)s[1023];
        atomicExch(&g_state[blockIdx.x], mine);
    }
    if (tid < 32) {
        int sum = 0;
        for (int j = tid; j < blockIdx.x; j += 32) {
            unsigned long long st;
            do { st = atomicAdd(&g_state[j], 0ULL); } while (!(st >> 32));
            sum += (int)(unsigned)st;
        }
#pragma unroll
        for (int o = 16; o > 0; o >>= 1) sum += __shfl_xor_sync(0xffffffffu, sum, o);
        if (tid == 0) s_prev = sum;
    }
    __syncthreads();
    int val = s[tid] + s_prev;          // inclusive padded offset (= off[i+1])
    if (i < NN) {
        g_off[i + 1] = val;
        // fill this row's pad slots with the dummy zero row offset
        for (int p = val - (v - dv); p < val; p++) g_col[p] = NN * 256;
    }
    if (i == 0) g_off[0] = 0;
}

// ------------- launch 3: CSR fill (atomic-free: off[row] + rank) -------------
__global__ void k_fill(const int* __restrict__ row, const int* __restrict__ col) {
    int e = blockIdx.x * blockDim.x + threadIdx.x;
    if (e < NE) {
        int r = row[e];
        int p = g_off[r] + g_rank[e];
        g_col[p] = col[e] << 8;
    }
}

// ------------- aggregation: warp per row, both towers (R15 shape) ------------
__device__ __forceinline__ void quadAB(const char* xb, int4 c, float2& A, float2& B) {
    const char* p0 = xb + (unsigned)c.x;
    const char* p1 = xb + (unsigned)c.y;
    const char* p2 = xb + (unsigned)c.z;
    const char* p3 = xb + (unsigned)c.w;
    __half2 a0 = *(const __half2*)p0;
    __half2 a1 = *(const __half2*)p1;
    __half2 a2 = *(const __half2*)p2;
    __half2 a3 = *(const __half2*)p3;
    __half2 b0 = *(const __half2*)(p0 + 128);
    __half2 b1 = *(const __half2*)(p1 + 128);
    __half2 b2 = *(const __half2*)(p2 + 128);
    __half2 b3 = *(const __half2*)(p3 + 128);
    __half2 qA = __hadd2(__hadd2(a0, a1), __hadd2(a2, a3));
    __half2 qB = __hadd2(__hadd2(b0, b1), __hadd2(b2, b3));
    A = add2(A, __half22float2(qA));
    B = add2(B, __half22float2(qB));
}

__global__ void __launch_bounds__(512)
k_agg() {
    int r = (blockIdx.x * 512 + threadIdx.x) >> 5;
    if (r >= NN) return;
    int lane = threadIdx.x & 31;
    const char* xb = (const char*)g_x + lane * 4;
    int beg = g_off[r], end = g_off[r + 1];      // multiple of 8 edges
    float2 A = {0.f, 0.f}, B = {0.f, 0.f};
    for (int e = beg; e < end; e += 8) {
        int4 ca = *(const int4*)(g_col + e);
        int4 cb = *(const int4*)(g_col + e + 4);
        quadAB(xb, ca, A, B);
        quadAB(xb, cb, A, B);
    }
    float invd = __fdividef(1.0f, (float)g_deg[r]);
    g_agg[r * 64 + lane]      = __float22half2_rn(make_float2(A.x * invd, A.y * invd));
    g_agg[r * 64 + 32 + lane] = __float22half2_rn(make_float2(B.x * invd, B.y * invd));
}

// ------------- dense via tensor cores (mma.sync m16n8k16 f16->f32) ----------
__device__ __forceinline__ void ldmA(uint32_t addr, uint32_t& a0, uint32_t& a1,
                                     uint32_t& a2, uint32_t& a3) {
    asm volatile("ldmatrix.sync.aligned.m8n8.x4.shared.b16 {%0,%1,%2,%3}, [%4];"
                 : "=r"(a0), "=r"(a1), "=r"(a2), "=r"(a3) : "r"(addr));
}
__device__ __forceinline__ void ldmB(uint32_t addr, uint32_t& b0, uint32_t& b1) {
    asm volatile("ldmatrix.sync.aligned.m8n8.x2.trans.shared.b16 {%0,%1}, [%2];"
                 : "=r"(b0), "=r"(b1) : "r"(addr));
}
__device__ __forceinline__ void hmma(float& c0, float& c1, float& c2, float& c3,
                                     uint32_t a0, uint32_t a1, uint32_t a2, uint32_t a3,
                                     uint32_t b0, uint32_t b1) {
    asm volatile("mma.sync.aligned.m16n8k16.row.col.f32.f16.f16.f32 "
                 "{%0,%1,%2,%3}, {%4,%5,%6,%7}, {%8,%9}, {%0,%1,%2,%3};"
                 : "+f"(c0), "+f"(c1), "+f"(c2), "+f"(c3)
                 : "r"(a0), "r"(a1), "r"(a2), "r"(a3), "r"(b0), "r"(b1));
}

__device__ __forceinline__ void mv_mma(uint32_t uA, uint32_t uWm, float* c, int lane) {
    int r = lane & 15;
    int hiA = lane >> 4;
    int rsw = r & 7;
#pragma unroll
    for (int s = 0; s < 4; s++) {
        uint32_t a0, a1, a2, a3;
        ldmA(uA + r * 128 + (((2 * s + hiA) ^ rsw) << 4), a0, a1, a2, a3);
        uint32_t rowB = uWm + (16 * s + r) * 128;
#pragma unroll
        for (int j = 0; j < 8; j++) {
            uint32_t b0, b1;
            ldmB(rowB + ((j ^ rsw) << 4), b0, b1);
            hmma(c[j * 4], c[j * 4 + 1], c[j * 4 + 2], c[j * 4 + 3],
                 a0, a1, a2, a3, b0, b1);
        }
    }
}

#define DENSE_SMEM_BYTES (24576 + 8 * 4096)

__global__ void __launch_bounds__(256, 2)
k_dense(const float* __restrict__ Wv, const float* __restrict__ Bv,
        const float* __restrict__ Wt, const float* __restrict__ Bt) {
    extern __shared__ char sm[];
    int tower = blockIdx.y;
    const float* W = tower ? Wt : Wv;
    const float* Bb = tower ? Bt : Bv;
    int t = threadIdx.x;

    __half* Wsm = (__half*)sm;
    for (int idx = t; idx < 3 * 4096; idx += 256) {
        int m = idx >> 12;
        int n = (idx >> 6) & 63;
        int k = idx & 63;
        int chunk = (n >> 3) ^ (k & 7);
        Wsm[m * 4096 + k * 64 + chunk * 8 + (n & 7)] = __float2half_rn(W[idx]);
    }
    __syncthreads();

    int lane = t & 31, warp = t >> 5;
    char* bufX = sm + 24576 + warp * 4096;
    char* bufA = bufX + 2048;
    uint32_t uW = (uint32_t)__cvta_generic_to_shared(Wsm);
    uint32_t uX = (uint32_t)__cvta_generic_to_shared(bufX);
    uint32_t uA = (uint32_t)__cvta_generic_to_shared(bufA);

    const char* xg = (const char*)g_x + tower * 128;
    const char* ag = (const char*)g_agg + tower * 128;
    char* xo = (char*)g_x + tower * 128;

    const float* b0p = Bb;
    const float* b1p = Bb + 64;
    const float* b2p = Bb + 128;
    int cp = lane & 3;
    int rl = lane >> 2;
    int rlsw = rl & 7;

    for (int g = blockIdx.x * 8 + warp; g < NN / 16; g += gridDim.x * 8) {
        int rbase = g * 16;
#pragma unroll
        for (int i = 0; i < 4; i++) {
            int idx = i * 32 + lane;
            int r = idx >> 3, c = idx & 7;
            uint4 vx = *(const uint4*)(xg + (size_t)(rbase + r) * 256 + c * 16);
            uint4 va = *(const uint4*)(ag + (size_t)(rbase + r) * 256 + c * 16);
            int csw = c ^ (r & 7);
            *(uint4*)(bufX + r * 128 + csw * 16) = vx;
            *(uint4*)(bufA + r * 128 + csw * 16) = va;
        }
        __syncwarp();

        // ---- mv1: xh = leaky(x@W1^T + b1) + id
        float xh[32];
#pragma unroll
        for (int i = 0; i < 32; i++) xh[i] = 0.f;
        mv_mma(uX, uW + 8192, xh, lane);
        int row0 = rbase + rl;
#pragma unroll
        for (int j = 0; j < 8; j++) {
            float2 bb = ((const float2*)b1p)[j * 4 + cp];
            float2 i0 = __half22float2(g_idh[row0 * 32 + j * 4 + cp]);
            float2 i1 = __half22float2(g_idh[(row0 + 8) * 32 + j * 4 + cp]);
            xh[j * 4 + 0] = leaky(xh[j * 4 + 0] + bb.x) + i0.x;
            xh[j * 4 + 1] = leaky(xh[j * 4 + 1] + bb.y) + i0.y;
            xh[j * 4 + 2] = leaky(xh[j * 4 + 2] + bb.x) + i1.x;
            xh[j * 4 + 3] = leaky(xh[j * 4 + 3] + bb.y) + i1.y;
        }

        // ---- mv0: h = leaky(agg@W0^T + b0) -> fp16 restage into bufX
        float c2[32];
#pragma unroll
        for (int i = 0; i < 32; i++) c2[i] = 0.f;
        mv_mma(uA, uW, c2, lane);
        __syncwarp();
#pragma unroll
        for (int j = 0; j < 8; j++) {
            float2 bb = ((const float2*)b0p)[j * 4 + cp];
            __half2 h0 = __floats2half2_rn(leaky(c2[j * 4 + 0] + bb.x),
                                           leaky(c2[j * 4 + 1] + bb.y));
            __half2 h1 = __floats2half2_rn(leaky(c2[j * 4 + 2] + bb.x),
                                           leaky(c2[j * 4 + 3] + bb.y));
            int ch = (j ^ rlsw) << 4;
            *(__half2*)(bufX + rl * 128 + ch + cp * 4) = h0;
            *(__half2*)(bufX + (rl + 8) * 128 + ch + cp * 4) = h1;
        }
        __syncwarp();

        // ---- mv2: out = leaky(h@W2^T + b2 + xh)
#pragma unroll
        for (int j = 0; j < 8; j++) {
            float2 bb = ((const float2*)b2p)[j * 4 + cp];
            xh[j * 4 + 0] += bb.x;
            xh[j * 4 + 1] += bb.y;
            xh[j * 4 + 2] += bb.x;
            xh[j * 4 + 3] += bb.y;
        }
        mv_mma(uX, uW + 16384, xh, lane);
#pragma unroll
        for (int j = 0; j < 8; j++) {
            __half2 o0 = __floats2half2_rn(leaky(xh[j * 4 + 0]), leaky(xh[j * 4 + 1]));
            __half2 o1 = __floats2half2_rn(leaky(xh[j * 4 + 2]), leaky(xh[j * 4 + 3]));
            *(__half2*)(xo + (size_t)row0 * 256 + (j * 4 + cp) * 4) = o0;
            *(__half2*)(xo + (size_t)(row0 + 8) * 256 + (j * 4 + cp) * 4) = o1;
        }
    }
}

// ------------- final combine (float4 stores) ----------------------------------
__global__ void k_combine(float4* __restrict__ out) {
    int i = blockIdx.x * blockDim.x + threadIdx.x;
    if (i < NN * 16) {
        int node = i >> 4, j = (i & 15) * 2;
        float2 a0 = __half22float2(g_x[node * 64 + j]);
        float2 a1 = __half22float2(g_x[node * 64 + j + 1]);
        float2 b0 = __half22float2(g_x[node * 64 + 32 + j]);
        float2 b1 = __half22float2(g_x[node * 64 + 32 + j + 1]);
        out[i] = make_float4(0.5f * (a0.x + b0.x), 0.5f * (a0.y + b0.y),
                             0.5f * (a1.x + b1.x), 0.5f * (a1.y + b1.y));
    }
}

// ------------- launch --------------------------------------------------------
extern "C" void kernel_launch(void* const* d_in, const int* in_sizes, int n_in,
                              void* d_out, int out_size) {
    const float* v_feat = (const float*)d_in[0];
    const float* t_feat = (const float*)d_in[1];
    const float* id_emb = (const float*)d_in[2];
    const float* v_pref = (const float*)d_in[3];
    const float* t_pref = (const float*)d_in[4];
    const float* v_W    = (const float*)d_in[5];
    const float* v_b    = (const float*)d_in[6];
    const float* t_W    = (const float*)d_in[7];
    const float* t_b    = (const float*)d_in[8];
    const int*   edges  = (const int*)d_in[9];
    const int* row = edges;
    const int* col = edges + NE;
    float4* out = (float4*)d_out;

    void *degp, *statep;
    cudaGetSymbolAddress(&degp, g_deg);
    cudaGetSymbolAddress(&statep, g_state);

    static int attr_done = 0;
    if (!attr_done) {
        cudaFuncSetAttribute(k_dense, cudaFuncAttributeMaxDynamicSharedMemorySize,
                             DENSE_SMEM_BYTES);
        attr_done = 1;
    }

    cudaMemsetAsync(degp, 0, NN * sizeof(int));
    cudaMemsetAsync(statep, 0, NB_SCAN * sizeof(unsigned long long));

    k_init_hist<<<20000, 256>>>(v_pref, v_feat, t_pref, t_feat, id_emb, row);
    k_scan<<<NB_SCAN, 1024>>>();
    k_fill<<<(NE + 255) / 256, 256>>>(row, col);

    dim3 dgrid(148, 2);
    for (int layer = 0; layer < 2; layer++) {
        k_agg<<<5000, 512>>>();
        k_dense<<<dgrid, 256, DENSE_SMEM_BYTES>>>(
            v_W + layer * 3 * 4096, v_b + layer * 3 * 64,
            t_W + layer * 3 * 4096, t_b + layer * 3 * 64);
    }

    k_combine<<<(NN * 16 + 255) / 256, 256>>>(out);
}